// round 10
// baseline (speedup 1.0000x reference)
#include <cuda_runtime.h>
#include <cstdint>

#define SEQ_LEN 12
#define HD   128
#define NPB  32            // pedestrians per CTA
#define NTH  256
#define APITCH 136         // A-tile pitch in floats (phase-clean for permuted LDS.64)

// Fragment-ordered tf32 W_hh image: frag_id = (cw*8 + g*2 + nt)*16 + ks,
// lane l holds float2 {b0,b1}: j = g*128+cw*16+nt*8+(l>>2), k = ks*8+(l&3)+4*p
__device__ __align__(16) float g_Wf[65536];
__device__ __align__(16) float4 g_tab[512];

__device__ __forceinline__ float rtf32(float x) {
    uint32_t u = __float_as_uint(x);
    u = (u + 0x1000u) & 0xFFFFE000u;
    return __uint_as_float(u);
}
// k-permutation within an 8-k block: pairs (t, t+4) made adjacent
__device__ __forceinline__ int sigma_k(int k) {
    int kl = k & 7;
    return (k & ~7) + ((kl < 4) ? (2 * kl) : (2 * (kl - 4) + 1));
}

__global__ void prep_kernel(const float* __restrict__ w_ih, const float* __restrict__ w_hh,
                            const float* __restrict__ b_ih, const float* __restrict__ b_hh,
                            const float* __restrict__ w_se, const float* __restrict__ b_se,
                            const float* __restrict__ w_hp) {
    int idx = blockIdx.x * blockDim.x + threadIdx.x;
    if (idx < 65536) {
        int p   = idx & 1;
        int l   = (idx >> 1) & 31;
        int ks  = (idx >> 6) & 15;
        int nt  = (idx >> 10) & 1;
        int g   = (idx >> 11) & 3;
        int cw  = (idx >> 13) & 7;
        int j   = g * 128 + cw * 16 + nt * 8 + (l >> 2);
        int k   = ks * 8 + (l & 3) + 4 * p;        // m16n8k8 B: b0 k=tig, b1 k=tig+4
        g_Wf[idx] = rtf32(w_hh[j * HD + k]);
    }
    if (idx < 512) {
        int j = idx;
        float bx = b_ih[j] + b_hh[j];
        float wy = 0.f, wz = 0.f;
        #pragma unroll 4
        for (int e = 0; e < 64; e++) {
            float w = w_ih[j * 64 + e];
            bx = fmaf(w, b_se[e], bx);
            wy = fmaf(w, w_se[e * 2 + 0], wy);
            wz = fmaf(w, w_se[e * 2 + 1], wz);
        }
        float ww = (j < 256) ? w_hp[j] : 0.f;
        g_tab[j] = make_float4(bx, wy, wz, ww);
    }
}

__device__ __forceinline__ float tanh_ap(float x) {
    float y; asm("tanh.approx.f32 %0, %1;" : "=f"(y) : "f"(x)); return y;
}
__device__ __forceinline__ float sigm_ap(float x) { return fmaf(0.5f, tanh_ap(0.5f * x), 0.5f); }

__device__ __forceinline__ void mma8(float& d0, float& d1, float& d2, float& d3,
                                     uint32_t a0, uint32_t a1, uint32_t a2, uint32_t a3,
                                     uint32_t b0, uint32_t b1) {
    asm volatile("mma.sync.aligned.m16n8k8.row.col.f32.tf32.tf32.f32 "
                 "{%0,%1,%2,%3},{%4,%5,%6,%7},{%8,%9},{%0,%1,%2,%3};"
                 : "+f"(d0), "+f"(d1), "+f"(d2), "+f"(d3)
                 : "r"(a0), "r"(a1), "r"(a2), "r"(a3), "r"(b0), "r"(b1));
}

__global__ __launch_bounds__(NTH, 2)
void decoder_kernel(const float* __restrict__ lpr, const float* __restrict__ h0,
                    const float* __restrict__ c0,  const float* __restrict__ b_hp,
                    float* __restrict__ out, int N) {
    __shared__ float  A_s[NPB][APITCH];    // h, tf32-rounded, k-permuted columns
    __shared__ float4 tab_s[512];
    __shared__ float2 rel_s[NPB];
    __shared__ float2 part_s[8][NPB];

    const int tid  = threadIdx.x;
    const int cw   = tid >> 5;        // warp = col-warp: u-range cw*16..+15, all 4 gates
    const int lane = tid & 31;
    const int gid  = lane >> 2;
    const int tig  = lane & 3;
    const int pbase = blockIdx.x * NPB;

    // ---- prologue ----
    for (int i = tid; i < 512; i += NTH) tab_s[i] = g_tab[i];
    if (tid < NPB) rel_s[tid] = ((const float2*)lpr)[pbase + tid];
    for (int i = tid; i < NPB * HD; i += NTH) {
        int ml = i >> 7, u = i & 127;
        A_s[ml][sigma_k(u)] = rtf32(h0[(size_t)(pbase + ml) * HD + u]);
    }
    // creg[m2][rr][nt][cc]: ped = pbase + m2*16+gid+rr*8 ; u = cw*16+nt*8+2*tig+cc
    float creg[2][2][2][2];
    #pragma unroll
    for (int m2 = 0; m2 < 2; m2++)
        #pragma unroll
        for (int rr = 0; rr < 2; rr++) {
            int p = pbase + m2 * 16 + gid + rr * 8;
            #pragma unroll
            for (int nt = 0; nt < 2; nt++)
                #pragma unroll
                for (int cc = 0; cc < 2; cc++)
                    creg[m2][rr][nt][cc] = c0[(size_t)p * HD + cw * 16 + nt * 8 + 2 * tig + cc];
        }
    const float bhp0 = b_hp[0], bhp1 = b_hp[1];
    const float2* __restrict__ wf2 = (const float2*)g_Wf;
    const int wbase = cw * 128 * 32 + lane;     // per-thread fragment base (float2 units)

    // ---- software pipeline: two B-fragment banks, primed with ks=0, ks=1 ----
    float2 bA[8], bB[8];
    #pragma unroll
    for (int gn = 0; gn < 8; gn++) {
        bA[gn] = __ldg(&wf2[wbase + gn * 512]);          // ks=0
        bB[gn] = __ldg(&wf2[wbase + 32 + gn * 512]);     // ks=1
    }
    __syncthreads();

    for (int t = 0; t < SEQ_LEN; t++) {
        float acc[2][4][2][4];
        #pragma unroll
        for (int m2 = 0; m2 < 2; m2++)
            #pragma unroll
            for (int g = 0; g < 4; g++)
                #pragma unroll
                for (int nt = 0; nt < 2; nt++)
                    #pragma unroll
                    for (int q = 0; q < 4; q++) acc[m2][g][nt][q] = 0.f;

        // ---- gates = h @ Whh^T, B prefetched 2 half-iterations ahead.
        // B is step-invariant: ks=14/15 prefetch wraps to ks=0/1 for step t+1.
        #pragma unroll
        for (int kk = 0; kk < 16; kk += 2) {
            // -- even ks = kk: consume bA --
            {
                uint32_t a[2][4];
                #pragma unroll
                for (int m2 = 0; m2 < 2; m2++) {
                    float2 lo = *(const float2*)&A_s[m2 * 16 + gid    ][kk * 8 + 2 * tig];
                    float2 hi = *(const float2*)&A_s[m2 * 16 + gid + 8][kk * 8 + 2 * tig];
                    a[m2][0] = __float_as_uint(lo.x); a[m2][2] = __float_as_uint(lo.y);
                    a[m2][1] = __float_as_uint(hi.x); a[m2][3] = __float_as_uint(hi.y);
                }
                #pragma unroll
                for (int g = 0; g < 4; g++)
                    #pragma unroll
                    for (int nt = 0; nt < 2; nt++) {
                        uint32_t b0 = __float_as_uint(bA[g * 2 + nt].x);
                        uint32_t b1 = __float_as_uint(bA[g * 2 + nt].y);
                        #pragma unroll
                        for (int m2 = 0; m2 < 2; m2++)
                            mma8(acc[m2][g][nt][0], acc[m2][g][nt][1],
                                 acc[m2][g][nt][2], acc[m2][g][nt][3],
                                 a[m2][0], a[m2][1], a[m2][2], a[m2][3], b0, b1);
                    }
            }
            // prefetch ks = (kk+2) & 15 into bA
            {
                const int pk = ((kk + 2) & 15) * 32 + wbase;
                #pragma unroll
                for (int gn = 0; gn < 8; gn++)
                    bA[gn] = __ldg(&wf2[pk + gn * 512]);
            }
            // -- odd ks = kk+1: consume bB --
            {
                uint32_t a[2][4];
                #pragma unroll
                for (int m2 = 0; m2 < 2; m2++) {
                    float2 lo = *(const float2*)&A_s[m2 * 16 + gid    ][(kk + 1) * 8 + 2 * tig];
                    float2 hi = *(const float2*)&A_s[m2 * 16 + gid + 8][(kk + 1) * 8 + 2 * tig];
                    a[m2][0] = __float_as_uint(lo.x); a[m2][2] = __float_as_uint(lo.y);
                    a[m2][1] = __float_as_uint(hi.x); a[m2][3] = __float_as_uint(hi.y);
                }
                #pragma unroll
                for (int g = 0; g < 4; g++)
                    #pragma unroll
                    for (int nt = 0; nt < 2; nt++) {
                        uint32_t b0 = __float_as_uint(bB[g * 2 + nt].x);
                        uint32_t b1 = __float_as_uint(bB[g * 2 + nt].y);
                        #pragma unroll
                        for (int m2 = 0; m2 < 2; m2++)
                            mma8(acc[m2][g][nt][0], acc[m2][g][nt][1],
                                 acc[m2][g][nt][2], acc[m2][g][nt][3],
                                 a[m2][0], a[m2][1], a[m2][2], a[m2][3], b0, b1);
                    }
            }
            // prefetch ks = (kk+3) & 15 into bB
            {
                const int pk = ((kk + 3) & 15) * 32 + wbase;
                #pragma unroll
                for (int gn = 0; gn < 8; gn++)
                    bB[gn] = __ldg(&wf2[pk + gn * 512]);
            }
        }
        __syncthreads();   // all A reads done before h overwrite

        // ---- epilogue ----
        float2 relv[2][2];
        #pragma unroll
        for (int m2 = 0; m2 < 2; m2++)
            #pragma unroll
            for (int rr = 0; rr < 2; rr++)
                relv[m2][rr] = rel_s[m2 * 16 + gid + rr * 8];

        float pa0[2][2] = {{0.f,0.f},{0.f,0.f}}, pa1[2][2] = {{0.f,0.f},{0.f,0.f}};

        #pragma unroll
        for (int nt = 0; nt < 2; nt++)
            #pragma unroll
            for (int cc = 0; cc < 2; cc++) {
                const int u  = cw * 16 + nt * 8 + 2 * tig + cc;
                const int uc = cw * 16 + sigma_k(nt * 8 + 2 * tig + cc);
                float4 tI = tab_s[u], tF = tab_s[128 + u], tG = tab_s[256 + u], tO = tab_s[384 + u];
                #pragma unroll
                for (int m2 = 0; m2 < 2; m2++)
                    #pragma unroll
                    for (int rr = 0; rr < 2; rr++) {
                        float2 rl = relv[m2][rr];
                        int q = rr * 2 + cc;
                        float gi = acc[m2][0][nt][q] + tI.x + rl.x * tI.y + rl.y * tI.z;
                        float gf = acc[m2][1][nt][q] + tF.x + rl.x * tF.y + rl.y * tF.z;
                        float gg = acc[m2][2][nt][q] + tG.x + rl.x * tG.y + rl.y * tG.z;
                        float go = acc[m2][3][nt][q] + tO.x + rl.x * tO.y + rl.y * tO.z;
                        float c  = fmaf(sigm_ap(gf), creg[m2][rr][nt][cc],
                                        sigm_ap(gi) * tanh_ap(gg));
                        creg[m2][rr][nt][cc] = c;
                        float h = sigm_ap(go) * tanh_ap(c);
                        A_s[m2 * 16 + gid + rr * 8][uc] = rtf32(h);
                        pa0[m2][rr] = fmaf(h, tI.w, pa0[m2][rr]);
                        pa1[m2][rr] = fmaf(h, tF.w, pa1[m2][rr]);
                    }
            }

        // reduce w_hp partials over the 4 tig lanes
        #pragma unroll
        for (int m2 = 0; m2 < 2; m2++)
            #pragma unroll
            for (int rr = 0; rr < 2; rr++) {
                float p0 = pa0[m2][rr], p1 = pa1[m2][rr];
                p0 += __shfl_xor_sync(0xFFFFFFFFu, p0, 1);
                p0 += __shfl_xor_sync(0xFFFFFFFFu, p0, 2);
                p1 += __shfl_xor_sync(0xFFFFFFFFu, p1, 1);
                p1 += __shfl_xor_sync(0xFFFFFFFFu, p1, 2);
                if (tig == 0)
                    part_s[cw][m2 * 16 + gid + rr * 8] = make_float2(p0, p1);
            }
        __syncthreads();

        if (tid < NPB) {
            float r0 = bhp0, r1 = bhp1;
            #pragma unroll
            for (int q = 0; q < 8; q++) {
                float2 v = part_s[q][tid];
                r0 += v.x; r1 += v.y;
            }
            rel_s[tid] = make_float2(r0, r1);
            ((float2*)out)[(size_t)t * N + pbase + tid] = make_float2(r0, r1);
        }
        __syncthreads();
    }
}

extern "C" void kernel_launch(void* const* d_in, const int* in_sizes, int n_in,
                              void* d_out, int out_size) {
    // order: last_pos, last_pos_rel, h0, c0, w_ih, w_hh, b_ih, b_hh, w_se, b_se, w_hp, b_hp
    const float* lpr  = (const float*)d_in[1];
    const float* h0   = (const float*)d_in[2];
    const float* c0   = (const float*)d_in[3];
    const float* w_ih = (const float*)d_in[4];
    const float* w_hh = (const float*)d_in[5];
    const float* b_ih = (const float*)d_in[6];
    const float* b_hh = (const float*)d_in[7];
    const float* w_se = (const float*)d_in[8];
    const float* b_se = (const float*)d_in[9];
    const float* w_hp = (const float*)d_in[10];
    const float* b_hp = (const float*)d_in[11];
    float* out = (float*)d_out;

    int N = in_sizes[0] / 2;   // 65536

    prep_kernel<<<65536 / 256, 256>>>(w_ih, w_hh, b_ih, b_hh, w_se, b_se, w_hp);
    decoder_kernel<<<N / NPB, NTH>>>(lpr, h0, c0, b_hp, out, N);
}

// round 12
// speedup vs baseline: 1.7018x; 1.7018x over previous
#include <cuda_runtime.h>
#include <cuda_fp16.h>
#include <cstdint>

#define SEQ_LEN 12
#define HD   128
#define NPB  32            // pedestrians per CTA
#define NTH  256
#define APH  144           // A-tile pitch in halves (288B rows; conflict-free LDS.64)

// Fragment-ordered fp16 W_hh image, uint2 units:
// idx = ((cw*8 + gn)*8 + kc)*32 + lane ; gn = g*2+nt
// lane l: b0 = {W[j][k0],W[j][k0+1]}, b1 = {W[j][k0+8],W[j][k0+9]},
//         j = g*128+cw*16+nt*8+(l>>2), k0 = kc*16 + 2*(l&3)
__device__ __align__(16) uint2  g_Wh[16384];
__device__ __align__(16) float4 g_tab[512];

// sigma16: within each 16-k chunk, place pairs {2t,2t+1},{2t+8,2t+9} adjacently
__device__ __forceinline__ int sigma16(int u) {
    int kl = u & 15, t = (kl & 7) >> 1, b = kl & 1, hi = (kl >> 3) & 1;
    return (u & ~15) + 4 * t + 2 * hi + b;
}

__global__ void prep_kernel(const float* __restrict__ w_ih, const float* __restrict__ w_hh,
                            const float* __restrict__ b_ih, const float* __restrict__ b_hh,
                            const float* __restrict__ w_se, const float* __restrict__ b_se,
                            const float* __restrict__ w_hp) {
    int idx = blockIdx.x * blockDim.x + threadIdx.x;
    if (idx < 16384) {
        int l  = idx & 31;
        int kc = (idx >> 5) & 7;
        int gn = (idx >> 8) & 7;
        int cw = (idx >> 11) & 7;
        int g = gn >> 1, nt = gn & 1;
        int j  = g * 128 + cw * 16 + nt * 8 + (l >> 2);
        int k0 = kc * 16 + 2 * (l & 3);
        __half2 b0 = __floats2half2_rn(w_hh[j * HD + k0],     w_hh[j * HD + k0 + 1]);
        __half2 b1 = __floats2half2_rn(w_hh[j * HD + k0 + 8], w_hh[j * HD + k0 + 9]);
        uint2 v;
        v.x = *(const uint32_t*)&b0;
        v.y = *(const uint32_t*)&b1;
        g_Wh[idx] = v;
    }
    if (idx < 512) {
        int j = idx;
        float bx = b_ih[j] + b_hh[j];
        float wy = 0.f, wz = 0.f;
        #pragma unroll 4
        for (int e = 0; e < 64; e++) {
            float w = w_ih[j * 64 + e];
            bx = fmaf(w, b_se[e], bx);
            wy = fmaf(w, w_se[e * 2 + 0], wy);
            wz = fmaf(w, w_se[e * 2 + 1], wz);
        }
        float ww = (j < 256) ? w_hp[j] : 0.f;
        g_tab[j] = make_float4(bx, wy, wz, ww);
    }
}

__device__ __forceinline__ float tanh_ap(float x) {
    float y; asm("tanh.approx.f32 %0, %1;" : "=f"(y) : "f"(x)); return y;
}
__device__ __forceinline__ float sigm_ap(float x) { return fmaf(0.5f, tanh_ap(0.5f * x), 0.5f); }

__device__ __forceinline__ void mma16(float& d0, float& d1, float& d2, float& d3,
                                      uint32_t a0, uint32_t a1, uint32_t a2, uint32_t a3,
                                      uint32_t b0, uint32_t b1) {
    asm volatile("mma.sync.aligned.m16n8k16.row.col.f32.f16.f16.f32 "
                 "{%0,%1,%2,%3},{%4,%5,%6,%7},{%8,%9},{%0,%1,%2,%3};"
                 : "+f"(d0), "+f"(d1), "+f"(d2), "+f"(d3)
                 : "r"(a0), "r"(a1), "r"(a2), "r"(a3), "r"(b0), "r"(b1));
}

__global__ __launch_bounds__(NTH, 2)
void decoder_kernel(const float* __restrict__ lpr, const float* __restrict__ h0,
                    const float* __restrict__ c0,  const float* __restrict__ b_hp,
                    float* __restrict__ out, int N) {
    __shared__ __half A_s[NPB][APH];      // h fp16, sigma16-permuted k columns
    __shared__ float4 tab_s[512];
    __shared__ float2 rel_s[NPB];
    __shared__ float2 part_s[8][NPB];

    const int tid  = threadIdx.x;
    const int cw   = tid >> 5;        // warp = col-warp: u-range cw*16..+15, all 4 gates
    const int lane = tid & 31;
    const int gid  = lane >> 2;
    const int tig  = lane & 3;
    const int pbase = blockIdx.x * NPB;

    // ---- prologue ----
    for (int i = tid; i < 512; i += NTH) tab_s[i] = g_tab[i];
    if (tid < NPB) rel_s[tid] = ((const float2*)lpr)[pbase + tid];
    for (int i = tid; i < NPB * HD; i += NTH) {
        int ml = i >> 7, u = i & 127;
        A_s[ml][sigma16(u)] = __float2half_rn(h0[(size_t)(pbase + ml) * HD + u]);
    }
    // creg[m2][rr][nt][cc]: ped = pbase + m2*16+gid+rr*8 ; u = cw*16+nt*8+2*tig+cc
    float creg[2][2][2][2];
    #pragma unroll
    for (int m2 = 0; m2 < 2; m2++)
        #pragma unroll
        for (int rr = 0; rr < 2; rr++) {
            int p = pbase + m2 * 16 + gid + rr * 8;
            #pragma unroll
            for (int nt = 0; nt < 2; nt++)
                #pragma unroll
                for (int cc = 0; cc < 2; cc++)
                    creg[m2][rr][nt][cc] = c0[(size_t)p * HD + cw * 16 + nt * 8 + 2 * tig + cc];
        }
    const float bhp0 = b_hp[0], bhp1 = b_hp[1];
    const uint2* __restrict__ wf = (const uint2*)g_Wh;
    const int wbase = cw * 2048 + lane;    // uint2 units; frag(gn,kc) at +gn*256+kc*32

    // ---- software pipeline: two B banks, primed with kc=0, kc=1 ----
    uint2 bA[8], bB[8];
    #pragma unroll
    for (int gn = 0; gn < 8; gn++) {
        bA[gn] = __ldg(&wf[wbase + gn * 256]);         // kc=0
        bB[gn] = __ldg(&wf[wbase + 32 + gn * 256]);    // kc=1
    }
    __syncthreads();

    for (int t = 0; t < SEQ_LEN; t++) {
        float acc[2][4][2][4];
        #pragma unroll
        for (int m2 = 0; m2 < 2; m2++)
            #pragma unroll
            for (int g = 0; g < 4; g++)
                #pragma unroll
                for (int nt = 0; nt < 2; nt++)
                    #pragma unroll
                    for (int q = 0; q < 4; q++) acc[m2][g][nt][q] = 0.f;

        // ---- gates = h @ Whh^T (fp16 m16n8k16), 8 k-chunks, B prefetched 2 ahead
        // (B step-invariant: kc=6/7 prefetch wraps to kc=0/1 for step t+1)
        #pragma unroll
        for (int kk = 0; kk < 8; kk += 2) {
            // -- even chunk kc = kk: consume bA --
            {
                uint32_t a[2][4];
                #pragma unroll
                for (int m2 = 0; m2 < 2; m2++) {
                    uint2 lo = *(const uint2*)&A_s[m2 * 16 + gid    ][kk * 16 + 4 * tig];
                    uint2 hi = *(const uint2*)&A_s[m2 * 16 + gid + 8][kk * 16 + 4 * tig];
                    a[m2][0] = lo.x; a[m2][2] = lo.y;     // row g:   k-lo, k-hi
                    a[m2][1] = hi.x; a[m2][3] = hi.y;     // row g+8: k-lo, k-hi
                }
                #pragma unroll
                for (int g = 0; g < 4; g++)
                    #pragma unroll
                    for (int nt = 0; nt < 2; nt++) {
                        uint32_t b0 = bA[g * 2 + nt].x, b1 = bA[g * 2 + nt].y;
                        #pragma unroll
                        for (int m2 = 0; m2 < 2; m2++)
                            mma16(acc[m2][g][nt][0], acc[m2][g][nt][1],
                                  acc[m2][g][nt][2], acc[m2][g][nt][3],
                                  a[m2][0], a[m2][1], a[m2][2], a[m2][3], b0, b1);
                    }
            }
            {   // prefetch kc = (kk+2) & 7 into bA
                const int pk = wbase + ((kk + 2) & 7) * 32;
                #pragma unroll
                for (int gn = 0; gn < 8; gn++)
                    bA[gn] = __ldg(&wf[pk + gn * 256]);
            }
            // -- odd chunk kc = kk+1: consume bB --
            {
                uint32_t a[2][4];
                #pragma unroll
                for (int m2 = 0; m2 < 2; m2++) {
                    uint2 lo = *(const uint2*)&A_s[m2 * 16 + gid    ][(kk + 1) * 16 + 4 * tig];
                    uint2 hi = *(const uint2*)&A_s[m2 * 16 + gid + 8][(kk + 1) * 16 + 4 * tig];
                    a[m2][0] = lo.x; a[m2][2] = lo.y;
                    a[m2][1] = hi.x; a[m2][3] = hi.y;
                }
                #pragma unroll
                for (int g = 0; g < 4; g++)
                    #pragma unroll
                    for (int nt = 0; nt < 2; nt++) {
                        uint32_t b0 = bB[g * 2 + nt].x, b1 = bB[g * 2 + nt].y;
                        #pragma unroll
                        for (int m2 = 0; m2 < 2; m2++)
                            mma16(acc[m2][g][nt][0], acc[m2][g][nt][1],
                                  acc[m2][g][nt][2], acc[m2][g][nt][3],
                                  a[m2][0], a[m2][1], a[m2][2], a[m2][3], b0, b1);
                    }
            }
            {   // prefetch kc = (kk+3) & 7 into bB
                const int pk = wbase + ((kk + 3) & 7) * 32;
                #pragma unroll
                for (int gn = 0; gn < 8; gn++)
                    bB[gn] = __ldg(&wf[pk + gn * 256]);
            }
        }
        __syncthreads();   // all A reads done before h overwrite

        // ---- epilogue ----
        float2 relv[2][2];
        #pragma unroll
        for (int m2 = 0; m2 < 2; m2++)
            #pragma unroll
            for (int rr = 0; rr < 2; rr++)
                relv[m2][rr] = rel_s[m2 * 16 + gid + rr * 8];

        float pa0[2][2] = {{0.f,0.f},{0.f,0.f}}, pa1[2][2] = {{0.f,0.f},{0.f,0.f}};

        #pragma unroll
        for (int nt = 0; nt < 2; nt++)
            #pragma unroll
            for (int cc = 0; cc < 2; cc++) {
                const int u  = cw * 16 + nt * 8 + 2 * tig + cc;
                const int uc = sigma16(u);
                float4 tI = tab_s[u], tF = tab_s[128 + u], tG = tab_s[256 + u], tO = tab_s[384 + u];
                #pragma unroll
                for (int m2 = 0; m2 < 2; m2++)
                    #pragma unroll
                    for (int rr = 0; rr < 2; rr++) {
                        float2 rl = relv[m2][rr];
                        int q = rr * 2 + cc;
                        float gi = acc[m2][0][nt][q] + tI.x + rl.x * tI.y + rl.y * tI.z;
                        float gf = acc[m2][1][nt][q] + tF.x + rl.x * tF.y + rl.y * tF.z;
                        float gg = acc[m2][2][nt][q] + tG.x + rl.x * tG.y + rl.y * tG.z;
                        float go = acc[m2][3][nt][q] + tO.x + rl.x * tO.y + rl.y * tO.z;
                        float c  = fmaf(sigm_ap(gf), creg[m2][rr][nt][cc],
                                        sigm_ap(gi) * tanh_ap(gg));
                        creg[m2][rr][nt][cc] = c;
                        float h = sigm_ap(go) * tanh_ap(c);
                        A_s[m2 * 16 + gid + rr * 8][uc] = __float2half_rn(h);
                        pa0[m2][rr] = fmaf(h, tI.w, pa0[m2][rr]);
                        pa1[m2][rr] = fmaf(h, tF.w, pa1[m2][rr]);
                    }
            }

        // reduce w_hp partials over the 4 tig lanes
        #pragma unroll
        for (int m2 = 0; m2 < 2; m2++)
            #pragma unroll
            for (int rr = 0; rr < 2; rr++) {
                float p0 = pa0[m2][rr], p1 = pa1[m2][rr];
                p0 += __shfl_xor_sync(0xFFFFFFFFu, p0, 1);
                p0 += __shfl_xor_sync(0xFFFFFFFFu, p0, 2);
                p1 += __shfl_xor_sync(0xFFFFFFFFu, p1, 1);
                p1 += __shfl_xor_sync(0xFFFFFFFFu, p1, 2);
                if (tig == 0)
                    part_s[cw][m2 * 16 + gid + rr * 8] = make_float2(p0, p1);
            }
        __syncthreads();

        if (tid < NPB) {
            float r0 = bhp0, r1 = bhp1;
            #pragma unroll
            for (int q = 0; q < 8; q++) {
                float2 v = part_s[q][tid];
                r0 += v.x; r1 += v.y;
            }
            rel_s[tid] = make_float2(r0, r1);
            ((float2*)out)[(size_t)t * N + pbase + tid] = make_float2(r0, r1);
        }
        __syncthreads();
    }
}

extern "C" void kernel_launch(void* const* d_in, const int* in_sizes, int n_in,
                              void* d_out, int out_size) {
    // order: last_pos, last_pos_rel, h0, c0, w_ih, w_hh, b_ih, b_hh, w_se, b_se, w_hp, b_hp
    const float* lpr  = (const float*)d_in[1];
    const float* h0   = (const float*)d_in[2];
    const float* c0   = (const float*)d_in[3];
    const float* w_ih = (const float*)d_in[4];
    const float* w_hh = (const float*)d_in[5];
    const float* b_ih = (const float*)d_in[6];
    const float* b_hh = (const float*)d_in[7];
    const float* w_se = (const float*)d_in[8];
    const float* b_se = (const float*)d_in[9];
    const float* w_hp = (const float*)d_in[10];
    const float* b_hp = (const float*)d_in[11];
    float* out = (float*)d_out;

    int N = in_sizes[0] / 2;   // 65536

    prep_kernel<<<16384 / 256, 256>>>(w_ih, w_hh, b_ih, b_hh, w_se, b_se, w_hp);
    decoder_kernel<<<N / NPB, NTH>>>(lpr, h0, c0, b_hp, out, N);
}